// round 8
// baseline (speedup 1.0000x reference)
#include <cuda_runtime.h>
#include <cuda_fp16.h>
#include <cstdint>

// lct_fk round 8: round-7 structure + shared-memory twiddle table WT[16][17]
// (w^{j*k1} = e^{-2pi i j k1/256}) replacing the 120-FMA complex recurrence.
// Inverse FFT conjugates via compile-time sign fold. Everything else identical
// to round 7 (passed 184.8us / 3.34e-4).

#define LL 256u
#define VOLS 2

__device__ __half2 g_A[(size_t)VOLS * LL * LL * LL]; // 134 MB

__device__ const int BR4[16] = {0,8,4,12,2,10,6,14,1,9,5,13,3,11,7,15};

__device__ __forceinline__ float2 h2f(__half2 h) { return __half22float2(h); }
__device__ __forceinline__ __half2 f2h(float2 f) { return __floats2half2_rn(f.x, f.y); }

// Fill the per-block twiddle table: WT[j][k] = e^{-2pi i j k / 256}
#define FILL_WT(WT, tid)                                              \
    {                                                                 \
        int jj = (tid) >> 4, kk = (tid) & 15;                         \
        float sn_, cs_;                                               \
        __sincosf(-0.024543692606f * (float)(jj * kk), &sn_, &cs_);   \
        WT[jj][kk] = make_float2(cs_, sn_);                           \
    }                                                                 \
    __syncthreads();

// ---------------- 16-pt in-register DIT FFT (input bit-reversed) ------------
__device__ __forceinline__ void fft16(float2 r[16], float dir) {
    const float CT[8] = {1.f, 0.92387953f, 0.70710678f, 0.38268343f,
                         0.f, -0.38268343f, -0.70710678f, -0.92387953f};
    const float ST[8] = {0.f, -0.38268343f, -0.70710678f, -0.92387953f,
                         -1.f, -0.92387953f, -0.70710678f, -0.38268343f};
#pragma unroll
    for (int s = 1; s <= 4; ++s) {
        int half = 1 << (s - 1);
#pragma unroll
        for (int j = 0; j < 8; ++j) {
            int k = j & (half - 1);
            int i0 = ((j >> (s - 1)) << s) + k;
            int i1 = i0 + half;
            float cs = CT[k << (4 - s)];
            float sn = dir * ST[k << (4 - s)];
            float2 b = r[i1];
            float tx = b.x * cs - b.y * sn;
            float ty = b.x * sn + b.y * cs;
            float2 a = r[i0];
            r[i1] = make_float2(a.x - tx, a.y - ty);
            r[i0] = make_float2(a.x + tx, a.y + ty);
        }
    }
}

// inter-pass twiddle from shared table row (wrow = WT[j]); dir is a literal,
// so dir*wy folds into the FMA sign.
__device__ __forceinline__ void twiddle16(float2 r[16], const float2* wrow,
                                          float dir) {
#pragma unroll
    for (int k1 = 1; k1 < 16; ++k1) {
        float wx = wrow[k1].x;
        float wy = dir * wrow[k1].y;
        float2 a = r[k1];
        r[k1] = make_float2(a.x * wx - a.y * wy, a.x * wy + a.y * wx);
    }
}

// Full 256-pt FFT for one line handled by 16 threads (role j).
// Entry: r[BR4[n1]] = x[16*n1 + j]. Exit: r[k2] = X[j + 16*k2].
__device__ __forceinline__ void fft256_pass(float2 r[16], float2* Tline,
                                            const float2* wrow,
                                            int j, float dir) {
    fft16(r, dir);
    twiddle16(r, wrow, dir);
    __syncthreads();
#pragma unroll
    for (int k1 = 0; k1 < 16; ++k1) Tline[k1 * 17 + j] = r[k1];
    __syncthreads();
    float2 rr[16];
#pragma unroll
    for (int n2 = 0; n2 < 16; ++n2) rr[BR4[n2]] = Tline[j * 17 + n2];
    fft16(rr, dir);
#pragma unroll
    for (int k = 0; k < 16; ++k) r[k] = rr[k];
}

// ---------------- Pass 1: preprocess + x-FFT + x-filter ---------------------
__global__ void k_fwd_x(const float* __restrict__ in) {
    __shared__ float2 T[16][273];
    __shared__ float2 WT[16][17];
    int tid = threadIdx.x;
    FILL_WT(WT, tid)
    int j = tid & 15, ln = tid >> 4;
    unsigned h = blockIdx.x * 16 + ln, t = blockIdx.y, v = blockIdx.z;
    float g = (float)t * (1.0f / 127.0f);
    const float* src = in + (((v * 128u + t) * 128u + h) * 128u);
    float2 r[16];
#pragma unroll
    for (int n1 = 0; n1 < 16; ++n1) {
        float val = 0.0f;
        if (n1 < 8) {
            float f = src[16 * n1 + j];
            float xx = f * g * g;
            val = (xx > 0.0f) ? sqrtf(xx) : 0.0f;
        }
        r[BR4[n1]] = make_float2(val, 0.0f);
    }
    fft256_pass(r, T[ln], WT[j], j, 1.0f);
    __syncthreads();
#pragma unroll
    for (int k2 = 0; k2 < 16; ++k2) T[ln][j + 17 * k2] = r[k2]; // pidx(k)=k+(k>>4)
    __syncthreads();
    __half2* __restrict__ dst = g_A + (((v * LL + t) * LL + h) * LL);
#pragma unroll
    for (int k2 = 0; k2 < 16; ++k2) {
        int k = j + 16 * k2;
        float2 a = T[ln][k + (k >> 4)];
        float2 b = make_float2(0.f, 0.f);
        if (k != 128) { int km = (k - 1) & 255; b = T[ln][km + (km >> 4)]; }
        dst[k] = f2h(make_float2(0.5f * (a.x + b.x), 0.5f * (a.y + b.y)));
    }
}

// ---------------- Pass 2: h-FFT (reads h<128) + y-filter, writes all h ------
__global__ void k_fwd_h() {
    __shared__ float2 T[16][273];
    __shared__ float2 WT[16][17];
    int tid = threadIdx.x;
    FILL_WT(WT, tid)
    int tx = tid & 15, j = tid >> 4;
    unsigned x = blockIdx.x * 16 + tx, t = blockIdx.y, v = blockIdx.z;
    unsigned base = (v * LL + t) * LL * LL + x;
    float2 r[16];
#pragma unroll
    for (int n1 = 0; n1 < 16; ++n1) {
        unsigned hh = 16 * n1 + j;
        r[BR4[n1]] = (n1 < 8) ? h2f(g_A[base + hh * LL])
                              : make_float2(0.f, 0.f);
    }
    fft256_pass(r, T[tx], WT[j], j, 1.0f);
    __syncthreads();
#pragma unroll
    for (int k2 = 0; k2 < 16; ++k2) T[tx][j + 17 * k2] = r[k2];
    __syncthreads();
#pragma unroll
    for (int k2 = 0; k2 < 16; ++k2) {
        int k = j + 16 * k2;
        float2 a = T[tx][k + (k >> 4)];
        float2 b = make_float2(0.f, 0.f);
        if (k != 128) { int km = (k - 1) & 255; b = T[tx][km + (km >> 4)]; }
        g_A[base + (unsigned)k * LL] =
            f2h(make_float2(0.5f * (a.x + b.x), 0.5f * (a.y + b.y)));
    }
}

// ---- Pass 3 (fused): forward t-FFT -> Stolt z-resample -> inverse t-FFT ----
__global__ void k_t_samp() {
    __shared__ float2 T[16][273];
    __shared__ float2 WT[16][17];
    int tid = threadIdx.x;
    FILL_WT(WT, tid)
    int tx = tid & 15, j = tid >> 4;
    unsigned x = blockIdx.x * 16 + tx, h = blockIdx.y, v = blockIdx.z;
    unsigned base = v * LL * LL * LL + h * LL + x;

    float2 r[16];
#pragma unroll
    for (int n1 = 0; n1 < 16; ++n1) {
        unsigned tt = 16 * n1 + j;
        r[BR4[n1]] = (n1 < 8) ? h2f(g_A[base + tt * (LL * LL)])
                              : make_float2(0.f, 0.f);
    }
    fft256_pass(r, T[tx], WT[j], j, 1.0f);  // F[k] in r[k2], k = j+16*k2

    __syncthreads();
#pragma unroll
    for (int k2 = 0; k2 < 8; ++k2) {
        int k = j + 16 * k2;
        T[tx][k + (k >> 4)] = r[k2];        // stash k<128 spectrum
    }
    __syncthreads();

    int iy = ((int)h + 128) & 255;
    int ixs = ((int)x + 128) & 255;
    float gx = (float)(ixs - 128) * (1.0f / 128.0f);
    float gy = (float)(iy - 128) * (1.0f / 128.0f);
    float rxy = 0.1024f * (gx * gx + gy * gy);

#pragma unroll
    for (int n1 = 0; n1 < 16; ++n1) {
        int t = 16 * n1 + j;
        float2 s = make_float2(0.f, 0.f);
        if (t >= 1 && t < 128) {
            float gz = (float)t * (1.0f / 128.0f);
            float q = rxy + gz * gz;       // >= (1/128)^2
            float rq = rsqrtf(q);
            float gzn = q * rq;            // sqrt(q)
            float pzf = 128.0f * gzn + 127.5f;   // >= 128.5
            int z0 = (int)pzf;
            float dz = pzf - (float)z0;
            int p0 = z0 - 128, p1 = z0 - 127;    // p0 >= 0
            float2 S0 = (p0 <= 127) ? T[tx][p0 + (p0 >> 4)] : make_float2(0.f, 0.f);
            float2 S1 = (p1 <= 127) ? T[tx][p1 + (p1 >> 4)] : make_float2(0.f, 0.f);
            float sc = gz * rq;            // ~ gz / gzn
            s = make_float2((S0.x * (1.f - dz) + S1.x * dz) * sc,
                            (S0.y * (1.f - dz) + S1.y * dz) * sc);
        }
        r[BR4[n1]] = s;
    }
    fft256_pass(r, T[tx], WT[j], j, -1.0f);

    const float SC = 1.0f / 4096.0f;      // first chunk of 1/2^24
#pragma unroll
    for (int k2 = 0; k2 < 8; ++k2)
        g_A[base + (unsigned)(j + 16 * k2) * (LL * LL)] =
            f2h(make_float2(r[k2].x * SC, r[k2].y * SC));
}

// ---------------- Pass 4: inverse h-FFT (reads all h, writes h<128) ---------
__global__ void k_inv_h() {
    __shared__ float2 T[16][273];
    __shared__ float2 WT[16][17];
    int tid = threadIdx.x;
    FILL_WT(WT, tid)
    int tx = tid & 15, j = tid >> 4;
    unsigned x = blockIdx.x * 16 + tx, t = blockIdx.y, v = blockIdx.z;
    unsigned base = (v * LL + t) * LL * LL + x;
    float2 r[16];
#pragma unroll
    for (int n1 = 0; n1 < 16; ++n1)
        r[BR4[n1]] = h2f(g_A[base + (unsigned)(16 * n1 + j) * LL]);
    fft256_pass(r, T[tx], WT[j], j, -1.0f);
    const float SC = 1.0f / 4096.0f;      // second chunk of 1/2^24
#pragma unroll
    for (int k2 = 0; k2 < 8; ++k2)
        g_A[base + (unsigned)(j + 16 * k2) * LL] =
            f2h(make_float2(r[k2].x * SC, r[k2].y * SC));
}

// ---------------- Pass 5: inverse x-FFT + real crop ------------------------
__global__ void k_inv_x(float* __restrict__ out) {
    __shared__ float2 T[16][273];
    __shared__ float2 WT[16][17];
    int tid = threadIdx.x;
    FILL_WT(WT, tid)
    int j = tid & 15, ln = tid >> 4;
    unsigned h = blockIdx.x * 16 + ln, t = blockIdx.y, v = blockIdx.z;
    unsigned base = ((v * LL + t) * LL + h) * LL;
    float2 r[16];
#pragma unroll
    for (int n1 = 0; n1 < 16; ++n1)
        r[BR4[n1]] = h2f(g_A[base + 16 * n1 + j]);
    fft256_pass(r, T[ln], WT[j], j, -1.0f);
    float* dst = out + (((v * 128u + t) * 128u + h) * 128u);
#pragma unroll
    for (int k2 = 0; k2 < 8; ++k2)
        dst[j + 16 * k2] = r[k2].x;       // normalization fully folded upstream
}

extern "C" void kernel_launch(void* const* d_in, const int* in_sizes, int n_in,
                              void* d_out, int out_size) {
    (void)in_sizes; (void)n_in; (void)out_size;
    const float* in = (const float*)d_in[0];
    float* out = (float*)d_out;

    k_fwd_x<<<dim3(8, 128, VOLS), 256>>>(in);
    k_fwd_h<<<dim3(16, 128, VOLS), 256>>>();
    k_t_samp<<<dim3(16, 256, VOLS), 256>>>();
    k_inv_h<<<dim3(16, 128, VOLS), 256>>>();
    k_inv_x<<<dim3(8, 128, VOLS), 256>>>(out);
}

// round 9
// speedup vs baseline: 1.0141x; 1.0141x over previous
#include <cuda_runtime.h>
#include <cuda_fp16.h>
#include <cstdint>

// lct_fk round 9: identical to round 7 (best passing: 184.8us / 3.34e-4)
// plus __launch_bounds__(256, 5) to lift occupancy from 4 to 5 blocks/SM
// (regs 56 -> <=51; tiny spill tolerated, L1 has headroom).

#define LL 256u
#define VOLS 2

__device__ __half2 g_A[(size_t)VOLS * LL * LL * LL]; // 134 MB

__device__ const int BR4[16] = {0,8,4,12,2,10,6,14,1,9,5,13,3,11,7,15};

__device__ __forceinline__ float2 h2f(__half2 h) { return __half22float2(h); }
__device__ __forceinline__ __half2 f2h(float2 f) { return __floats2half2_rn(f.x, f.y); }

// ---------------- 16-pt in-register DIT FFT (input bit-reversed) ------------
__device__ __forceinline__ void fft16(float2 r[16], float dir) {
    const float CT[8] = {1.f, 0.92387953f, 0.70710678f, 0.38268343f,
                         0.f, -0.38268343f, -0.70710678f, -0.92387953f};
    const float ST[8] = {0.f, -0.38268343f, -0.70710678f, -0.92387953f,
                         -1.f, -0.92387953f, -0.70710678f, -0.38268343f};
#pragma unroll
    for (int s = 1; s <= 4; ++s) {
        int half = 1 << (s - 1);
#pragma unroll
        for (int j = 0; j < 8; ++j) {
            int k = j & (half - 1);
            int i0 = ((j >> (s - 1)) << s) + k;
            int i1 = i0 + half;
            float cs = CT[k << (4 - s)];
            float sn = dir * ST[k << (4 - s)];
            float2 b = r[i1];
            float tx = b.x * cs - b.y * sn;
            float ty = b.x * sn + b.y * cs;
            float2 a = r[i0];
            r[i1] = make_float2(a.x - tx, a.y - ty);
            r[i0] = make_float2(a.x + tx, a.y + ty);
        }
    }
}

// inter-pass twiddle via recurrence: r[k1] *= exp(dir * -2*pi*i * j*k1/256)
__device__ __forceinline__ void twiddle16(float2 r[16], int j, float dir) {
    float wy, wx;
    __sincosf(dir * -0.024543692606f * (float)j, &wy, &wx);
    float cx = wx, cy = wy;
#pragma unroll
    for (int k1 = 1; k1 < 16; ++k1) {
        float2 a = r[k1];
        r[k1] = make_float2(a.x * cx - a.y * cy, a.x * cy + a.y * cx);
        float nx = cx * wx - cy * wy;
        float ny = cx * wy + cy * wx;
        cx = nx; cy = ny;
    }
}

// Full 256-pt FFT for one line handled by 16 threads (role j).
// Entry: r[BR4[n1]] = x[16*n1 + j]. Exit: r[k2] = X[j + 16*k2].
__device__ __forceinline__ void fft256_pass(float2 r[16], float2* Tline,
                                            int j, float dir) {
    fft16(r, dir);
    twiddle16(r, j, dir);
    __syncthreads();
#pragma unroll
    for (int k1 = 0; k1 < 16; ++k1) Tline[k1 * 17 + j] = r[k1];
    __syncthreads();
    float2 rr[16];
#pragma unroll
    for (int n2 = 0; n2 < 16; ++n2) rr[BR4[n2]] = Tline[j * 17 + n2];
    fft16(rr, dir);
#pragma unroll
    for (int k = 0; k < 16; ++k) r[k] = rr[k];
}

// ---------------- Pass 1: preprocess + x-FFT + x-filter ---------------------
__global__ void __launch_bounds__(256, 5) k_fwd_x(const float* __restrict__ in) {
    __shared__ float2 T[16][273];
    int tid = threadIdx.x;
    int j = tid & 15, ln = tid >> 4;
    unsigned h = blockIdx.x * 16 + ln, t = blockIdx.y, v = blockIdx.z;
    float g = (float)t * (1.0f / 127.0f);
    const float* src = in + (((v * 128u + t) * 128u + h) * 128u);
    float2 r[16];
#pragma unroll
    for (int n1 = 0; n1 < 16; ++n1) {
        float val = 0.0f;
        if (n1 < 8) {
            float f = src[16 * n1 + j];
            float xx = f * g * g;
            val = (xx > 0.0f) ? sqrtf(xx) : 0.0f;
        }
        r[BR4[n1]] = make_float2(val, 0.0f);
    }
    fft256_pass(r, T[ln], j, 1.0f);
    __syncthreads();
#pragma unroll
    for (int k2 = 0; k2 < 16; ++k2) T[ln][j + 17 * k2] = r[k2]; // pidx(k)=k+(k>>4)
    __syncthreads();
    __half2* __restrict__ dst = g_A + (((v * LL + t) * LL + h) * LL);
#pragma unroll
    for (int k2 = 0; k2 < 16; ++k2) {
        int k = j + 16 * k2;
        float2 a = T[ln][k + (k >> 4)];
        float2 b = make_float2(0.f, 0.f);
        if (k != 128) { int km = (k - 1) & 255; b = T[ln][km + (km >> 4)]; }
        dst[k] = f2h(make_float2(0.5f * (a.x + b.x), 0.5f * (a.y + b.y)));
    }
}

// ---------------- Pass 2: h-FFT (reads h<128) + y-filter, writes all h ------
__global__ void __launch_bounds__(256, 5) k_fwd_h() {
    __shared__ float2 T[16][273];
    int tid = threadIdx.x;
    int tx = tid & 15, j = tid >> 4;
    unsigned x = blockIdx.x * 16 + tx, t = blockIdx.y, v = blockIdx.z;
    unsigned base = (v * LL + t) * LL * LL + x;
    float2 r[16];
#pragma unroll
    for (int n1 = 0; n1 < 16; ++n1) {
        unsigned hh = 16 * n1 + j;
        r[BR4[n1]] = (n1 < 8) ? h2f(g_A[base + hh * LL])
                              : make_float2(0.f, 0.f);
    }
    fft256_pass(r, T[tx], j, 1.0f);
    __syncthreads();
#pragma unroll
    for (int k2 = 0; k2 < 16; ++k2) T[tx][j + 17 * k2] = r[k2];
    __syncthreads();
#pragma unroll
    for (int k2 = 0; k2 < 16; ++k2) {
        int k = j + 16 * k2;
        float2 a = T[tx][k + (k >> 4)];
        float2 b = make_float2(0.f, 0.f);
        if (k != 128) { int km = (k - 1) & 255; b = T[tx][km + (km >> 4)]; }
        g_A[base + (unsigned)k * LL] =
            f2h(make_float2(0.5f * (a.x + b.x), 0.5f * (a.y + b.y)));
    }
}

// ---- Pass 3 (fused): forward t-FFT -> Stolt z-resample -> inverse t-FFT ----
__global__ void __launch_bounds__(256, 5) k_t_samp() {
    __shared__ float2 T[16][273];
    int tid = threadIdx.x;
    int tx = tid & 15, j = tid >> 4;
    unsigned x = blockIdx.x * 16 + tx, h = blockIdx.y, v = blockIdx.z;
    unsigned base = v * LL * LL * LL + h * LL + x;

    float2 r[16];
#pragma unroll
    for (int n1 = 0; n1 < 16; ++n1) {
        unsigned tt = 16 * n1 + j;
        r[BR4[n1]] = (n1 < 8) ? h2f(g_A[base + tt * (LL * LL)])
                              : make_float2(0.f, 0.f);
    }
    fft256_pass(r, T[tx], j, 1.0f);       // F[k] in r[k2], k = j+16*k2

    __syncthreads();
#pragma unroll
    for (int k2 = 0; k2 < 8; ++k2) {
        int k = j + 16 * k2;
        T[tx][k + (k >> 4)] = r[k2];      // stash k<128 spectrum
    }
    __syncthreads();

    int iy = ((int)h + 128) & 255;
    int ixs = ((int)x + 128) & 255;
    float gx = (float)(ixs - 128) * (1.0f / 128.0f);
    float gy = (float)(iy - 128) * (1.0f / 128.0f);
    float rxy = 0.1024f * (gx * gx + gy * gy);

#pragma unroll
    for (int n1 = 0; n1 < 16; ++n1) {
        int t = 16 * n1 + j;
        float2 s = make_float2(0.f, 0.f);
        if (t >= 1 && t < 128) {
            float gz = (float)t * (1.0f / 128.0f);
            float q = rxy + gz * gz;       // >= (1/128)^2
            float rq = rsqrtf(q);
            float gzn = q * rq;            // sqrt(q)
            float pzf = 128.0f * gzn + 127.5f;   // >= 128.5
            int z0 = (int)pzf;
            float dz = pzf - (float)z0;
            int p0 = z0 - 128, p1 = z0 - 127;    // p0 >= 0
            float2 S0 = (p0 <= 127) ? T[tx][p0 + (p0 >> 4)] : make_float2(0.f, 0.f);
            float2 S1 = (p1 <= 127) ? T[tx][p1 + (p1 >> 4)] : make_float2(0.f, 0.f);
            float sc = gz * rq;            // ~ gz / gzn
            s = make_float2((S0.x * (1.f - dz) + S1.x * dz) * sc,
                            (S0.y * (1.f - dz) + S1.y * dz) * sc);
        }
        r[BR4[n1]] = s;
    }
    fft256_pass(r, T[tx], j, -1.0f);

    const float SC = 1.0f / 4096.0f;      // first chunk of 1/2^24
#pragma unroll
    for (int k2 = 0; k2 < 8; ++k2)
        g_A[base + (unsigned)(j + 16 * k2) * (LL * LL)] =
            f2h(make_float2(r[k2].x * SC, r[k2].y * SC));
}

// ---------------- Pass 4: inverse h-FFT (reads all h, writes h<128) ---------
__global__ void __launch_bounds__(256, 5) k_inv_h() {
    __shared__ float2 T[16][273];
    int tid = threadIdx.x;
    int tx = tid & 15, j = tid >> 4;
    unsigned x = blockIdx.x * 16 + tx, t = blockIdx.y, v = blockIdx.z;
    unsigned base = (v * LL + t) * LL * LL + x;
    float2 r[16];
#pragma unroll
    for (int n1 = 0; n1 < 16; ++n1)
        r[BR4[n1]] = h2f(g_A[base + (unsigned)(16 * n1 + j) * LL]);
    fft256_pass(r, T[tx], j, -1.0f);
    const float SC = 1.0f / 4096.0f;      // second chunk of 1/2^24
#pragma unroll
    for (int k2 = 0; k2 < 8; ++k2)
        g_A[base + (unsigned)(j + 16 * k2) * LL] =
            f2h(make_float2(r[k2].x * SC, r[k2].y * SC));
}

// ---------------- Pass 5: inverse x-FFT + real crop ------------------------
__global__ void __launch_bounds__(256, 5) k_inv_x(float* __restrict__ out) {
    __shared__ float2 T[16][273];
    int tid = threadIdx.x;
    int j = tid & 15, ln = tid >> 4;
    unsigned h = blockIdx.x * 16 + ln, t = blockIdx.y, v = blockIdx.z;
    unsigned base = ((v * LL + t) * LL + h) * LL;
    float2 r[16];
#pragma unroll
    for (int n1 = 0; n1 < 16; ++n1)
        r[BR4[n1]] = h2f(g_A[base + 16 * n1 + j]);
    fft256_pass(r, T[ln], j, -1.0f);
    float* dst = out + (((v * 128u + t) * 128u + h) * 128u);
#pragma unroll
    for (int k2 = 0; k2 < 8; ++k2)
        dst[j + 16 * k2] = r[k2].x;       // normalization fully folded upstream
}

extern "C" void kernel_launch(void* const* d_in, const int* in_sizes, int n_in,
                              void* d_out, int out_size) {
    (void)in_sizes; (void)n_in; (void)out_size;
    const float* in = (const float*)d_in[0];
    float* out = (float*)d_out;

    k_fwd_x<<<dim3(8, 128, VOLS), 256>>>(in);
    k_fwd_h<<<dim3(16, 128, VOLS), 256>>>();
    k_t_samp<<<dim3(16, 256, VOLS), 256>>>();
    k_inv_h<<<dim3(16, 128, VOLS), 256>>>();
    k_inv_x<<<dim3(8, 128, VOLS), 256>>>(out);
}